// round 6
// baseline (speedup 1.0000x reference)
#include <cuda_runtime.h>
#include <math.h>

#define PH 7
#define PW 7
#define NC 256
#define MAXR 1024

// Per-ROI precomputed params: 8 floats each.
// [0]=x1s [1]=y1s [2]=bin_w [3]=bin_h [4]=H(int) [5]=plane base offset(int) [6]=lvl(int)
__device__ float g_roi_params[MAXR * 8];

__global__ void prep_kernel(const float* __restrict__ boxes, int R)
{
    int r = blockIdx.x * blockDim.x + threadIdx.x;
    if (r >= R) return;

    float bx1 = boxes[r * 4 + 0];
    float by1 = boxes[r * 4 + 1];
    float bx2 = boxes[r * 4 + 2];
    float by2 = boxes[r * 4 + 3];

    float area = (bx2 - bx1) * (by2 - by1);
    float s = sqrtf(area);
    float lf = floorf(4.0f + log2f(s / 224.0f + 1e-6f));
    lf = fminf(fmaxf(lf, 2.0f), 5.0f);
    int lvl = (int)lf - 2;

    int H; float scale;
    switch (lvl) {
        case 0:  H = 200; scale = 0.25f;    break;
        case 1:  H = 100; scale = 0.125f;   break;
        case 2:  H = 50;  scale = 0.0625f;  break;
        default: H = 25;  scale = 0.03125f; break;
    }

    int bidx = (2 * r) / R;
    int baseoff = bidx * NC * H * H;   // plane-group offset within the level tensor

    float x1s = bx1 * scale, y1s = by1 * scale;
    float roi_w = fmaxf(bx2 * scale - x1s, 1.0f);
    float roi_h = fmaxf(by2 * scale - y1s, 1.0f);

    float* p = g_roi_params + r * 8;
    p[0] = x1s;
    p[1] = y1s;
    p[2] = roi_w * (1.0f / PW);
    p[3] = roi_h * (1.0f / PH);
    p[4] = __int_as_float(H);
    p[5] = __int_as_float(baseoff);
    p[6] = __int_as_float(lvl);
}

// Block = one ROI. Warp w owns channels [w*32, w*32+32).
// Lanes 0..27 = (pw, sx, xtap) tap x-positions; y-geometry for all 7 ph is
// computed once into smem. Warp loops ph (outer) x 32 channels (inner);
// overlapping feature rows across ph stay resident in this SM's L1.
__global__ void __launch_bounds__(256) pooler_kernel(
    const float* __restrict__ x0, const float* __restrict__ x1,
    const float* __restrict__ x2, const float* __restrict__ x3,
    float* __restrict__ out, int R)
{
    __shared__ int   s_off[PH][4];   // row offsets (row*W) for rl0,rh0,rl1,rh1
    __shared__ float s_wy[PH][4];    // y-weights hy0,ly0,hy1,ly1 (0 if empty)

    int tid  = threadIdx.x;
    int warp = tid >> 5;
    int lane = tid & 31;
    int r = blockIdx.x;

    const float* prm = g_roi_params + r * 8;
    float x1s   = __ldg(&prm[0]);
    float y1s   = __ldg(&prm[1]);
    float bin_w = __ldg(&prm[2]);
    float bin_h = __ldg(&prm[3]);
    int H       = __float_as_int(__ldg(&prm[4]));
    int baseoff = __float_as_int(__ldg(&prm[5]));
    int lvl     = __float_as_int(__ldg(&prm[6]));
    int W = H;
    size_t HW = (size_t)H * W;

    const float* feat = (lvl == 0) ? x0 : (lvl == 1) ? x1 : (lvl == 2) ? x2 : x3;

    // y-geometry: 14 (ph, sy) pairs -> smem
    if (tid < PH * 2) {
        int ph = tid >> 1, sy = tid & 1;
        float y = y1s + ph * bin_h + (sy + 0.5f) * bin_h * 0.5f;
        bool ye = (y < -1.0f) || (y > (float)H);
        float yc = fmaxf(y, 0.0f);
        float yl0 = floorf(yc);
        int yl_, yh_; float l;
        if (yl0 >= (float)(H - 1)) { yl_ = H - 1; yh_ = H - 1; l = 0.0f; }
        else { yl_ = (int)yl0; yh_ = yl_ + 1; l = yc - yl0; }
        s_off[ph][2 * sy + 0] = yl_ * W;
        s_off[ph][2 * sy + 1] = yh_ * W;
        s_wy[ph][2 * sy + 0] = ye ? 0.0f : (1.0f - l);
        s_wy[ph][2 * sy + 1] = ye ? 0.0f : l;
    }
    __syncthreads();

    // lane x-geometry: lane = pw*4 + sx*2 + xtap (28 active)
    int pw = lane >> 2;
    int sx = (lane >> 1) & 1;
    int xt = lane & 1;
    float wx = 0.0f;
    int xoff = 0;
    if (lane < 28) {
        float x = x1s + pw * bin_w + (sx + 0.5f) * bin_w * 0.5f;
        bool xe = (x < -1.0f) || (x > (float)W);
        float xc = fmaxf(x, 0.0f);
        float xl0 = floorf(xc);
        int xl_, xh_; float l;
        if (xl0 >= (float)(W - 1)) { xl_ = W - 1; xh_ = W - 1; l = 0.0f; }
        else { xl_ = (int)xl0; xh_ = xl_ + 1; l = xc - xl0; }
        xoff = xt ? xh_ : xl_;
        wx = xe ? 0.0f : (xt ? l : (1.0f - l)) * 0.25f;  // fold 2x2 mean
    }

    int c0 = warp * 32;
    const float* base = feat + baseoff + (size_t)c0 * HW + xoff;
    bool writer = ((lane & 3) == 0) && (lane < 28);
    size_t obase0 = ((size_t)r * NC + c0) * (PH * PW) + pw;

    #pragma unroll
    for (int ph = 0; ph < PH; ph++) {
        float w0 = wx * s_wy[ph][0];
        float w1 = wx * s_wy[ph][1];
        float w2 = wx * s_wy[ph][2];
        float w3 = wx * s_wy[ph][3];
        const float* p0 = base + s_off[ph][0];
        const float* p1 = base + s_off[ph][1];
        const float* p2 = base + s_off[ph][2];
        const float* p3 = base + s_off[ph][3];
        size_t obase = obase0 + ph * PW;

        #pragma unroll 4
        for (int k = 0; k < 32; k++) {
            float v = w0 * __ldg(p0) + w1 * __ldg(p1)
                    + w2 * __ldg(p2) + w3 * __ldg(p3);
            v += __shfl_xor_sync(0xffffffffu, v, 1);
            v += __shfl_xor_sync(0xffffffffu, v, 2);
            if (writer) out[obase + (size_t)k * (PH * PW)] = v;
            p0 += HW; p1 += HW; p2 += HW; p3 += HW;
        }
    }
}

extern "C" void kernel_launch(void* const* d_in, const int* in_sizes, int n_in,
                              void* d_out, int out_size) {
    const float* x0    = (const float*)d_in[0];
    const float* x1    = (const float*)d_in[1];
    const float* x2    = (const float*)d_in[2];
    const float* x3    = (const float*)d_in[3];
    const float* boxes = (const float*)d_in[4];
    float* out = (float*)d_out;

    int R = in_sizes[4] / 4;    // B*N = 1024
    prep_kernel<<<(R + 255) / 256, 256>>>(boxes, R);
    pooler_kernel<<<R, 256>>>(x0, x1, x2, x3, out, R);
}

// round 8
// speedup vs baseline: 1.4255x; 1.4255x over previous
#include <cuda_runtime.h>
#include <math.h>

#define PH 7
#define PW 7
#define NC 256
#define MAXR 1024

// Per-ROI params: A = {x1s, y1s, bin_w, bin_h}, B = {H, baseoff, lvl, 0}
__device__ float4 g_params_a[MAXR];
__device__ int4   g_params_b[MAXR];

__global__ void prep_kernel(const float* __restrict__ boxes, int R)
{
    int r = blockIdx.x * blockDim.x + threadIdx.x;
    if (r >= R) return;

    float bx1 = boxes[r * 4 + 0];
    float by1 = boxes[r * 4 + 1];
    float bx2 = boxes[r * 4 + 2];
    float by2 = boxes[r * 4 + 3];

    float area = (bx2 - bx1) * (by2 - by1);
    float s = sqrtf(area);
    float lf = floorf(4.0f + log2f(s / 224.0f + 1e-6f));
    lf = fminf(fmaxf(lf, 2.0f), 5.0f);
    int lvl = (int)lf - 2;

    int H; float scale;
    switch (lvl) {
        case 0:  H = 200; scale = 0.25f;    break;
        case 1:  H = 100; scale = 0.125f;   break;
        case 2:  H = 50;  scale = 0.0625f;  break;
        default: H = 25;  scale = 0.03125f; break;
    }

    int bidx = (2 * r) / R;                 // B=2
    int baseoff = bidx * NC * H * H;

    float x1s = bx1 * scale, y1s = by1 * scale;
    float roi_w = fmaxf(bx2 * scale - x1s, 1.0f);
    float roi_h = fmaxf(by2 * scale - y1s, 1.0f);

    g_params_a[r] = make_float4(x1s, y1s, roi_w * (1.0f / PW), roi_h * (1.0f / PH));
    g_params_b[r] = make_int4(H, baseoff, lvl, 0);
}

// Block = (roi, ph); warp w = channels [w*32, w*32+32).
// Lanes 0..27 = (pw, sx, xtap) tap x-positions along the bin row.
// 4 feature rows per bin row, deduped to 3 when the two y-samples share a row
// (common for scaled ROI height < 14 px). 4-lane shfl finishes each bin.
__global__ void __launch_bounds__(256) pooler_kernel(
    const float* __restrict__ x0, const float* __restrict__ x1,
    const float* __restrict__ x2, const float* __restrict__ x3,
    float* __restrict__ out, int R)
{
    int bid  = blockIdx.x;
    int r    = bid / PH;
    int ph   = bid - r * PH;
    int warp = threadIdx.x >> 5;
    int lane = threadIdx.x & 31;

    float4 pa = g_params_a[r];
    int4   pb = g_params_b[r];
    float x1s = pa.x, y1s = pa.y, bin_w = pa.z, bin_h = pa.w;
    int H = pb.x, baseoff = pb.y, lvl = pb.z;
    int W = H;
    size_t HW = (size_t)H * W;

    const float* feat = (lvl == 0) ? x0 : (lvl == 1) ? x1 : (lvl == 2) ? x2 : x3;

    // y geometry for this ph: 2 samples -> up to 4 rows (uniform across warp)
    int   off[4];
    float wy[4];
    #pragma unroll
    for (int sy = 0; sy < 2; sy++) {
        float y = y1s + ph * bin_h + (sy + 0.5f) * bin_h * 0.5f;
        bool ye = (y < -1.0f) || (y > (float)H);
        float yc = fmaxf(y, 0.0f);
        float yl0 = floorf(yc);
        int yl_, yh_; float l;
        if (yl0 >= (float)(H - 1)) { yl_ = H - 1; yh_ = H - 1; l = 0.0f; }
        else { yl_ = (int)yl0; yh_ = yl_ + 1; l = yc - yl0; }
        off[2 * sy + 0] = yl_ * W;
        off[2 * sy + 1] = yh_ * W;
        wy[2 * sy + 0] = ye ? 0.0f : (1.0f - l);
        wy[2 * sy + 1] = ye ? 0.0f : l;
    }
    // merge shared middle row (yh0 == yl1) -> 3 loads
    bool merged = (off[1] == off[2]);
    if (merged) { wy[1] += wy[2]; off[2] = off[3]; wy[2] = wy[3]; }

    // lane x geometry: lane = pw*4 + sx*2 + xtap (28 active)
    int pw = lane >> 2;
    int sx = (lane >> 1) & 1;
    int xt = lane & 1;
    float wx = 0.0f;
    int xoff = 0;
    if (lane < 28) {
        float x = x1s + pw * bin_w + (sx + 0.5f) * bin_w * 0.5f;
        bool xe = (x < -1.0f) || (x > (float)W);
        float xc = fmaxf(x, 0.0f);
        float xl0 = floorf(xc);
        int xl_, xh_; float l;
        if (xl0 >= (float)(W - 1)) { xl_ = W - 1; xh_ = W - 1; l = 0.0f; }
        else { xl_ = (int)xl0; xh_ = xl_ + 1; l = xc - xl0; }
        xoff = xt ? xh_ : xl_;
        wx = xe ? 0.0f : (xt ? l : (1.0f - l)) * 0.25f;   // fold 2x2 mean
    }

    int c0 = warp * 32;
    const float* base = feat + baseoff + (size_t)c0 * HW + xoff;
    bool writer = ((lane & 3) == 0) && (lane < 28);
    size_t obase = ((size_t)r * NC + c0) * (PH * PW) + ph * PW + pw;

    float w0 = wx * wy[0], w1 = wx * wy[1], w2 = wx * wy[2], w3 = wx * wy[3];

    if (merged) {
        const float* p0 = base + off[0];
        const float* p1 = base + off[1];
        const float* p2 = base + off[2];
        #pragma unroll 4
        for (int k = 0; k < 32; k++) {
            float v = w0 * __ldg(p0) + w1 * __ldg(p1) + w2 * __ldg(p2);
            v += __shfl_xor_sync(0xffffffffu, v, 1);
            v += __shfl_xor_sync(0xffffffffu, v, 2);
            if (writer) out[obase + (size_t)k * (PH * PW)] = v;
            p0 += HW; p1 += HW; p2 += HW;
        }
    } else {
        const float* p0 = base + off[0];
        const float* p1 = base + off[1];
        const float* p2 = base + off[2];
        const float* p3 = base + off[3];
        #pragma unroll 4
        for (int k = 0; k < 32; k++) {
            float v = w0 * __ldg(p0) + w1 * __ldg(p1)
                    + w2 * __ldg(p2) + w3 * __ldg(p3);
            v += __shfl_xor_sync(0xffffffffu, v, 1);
            v += __shfl_xor_sync(0xffffffffu, v, 2);
            if (writer) out[obase + (size_t)k * (PH * PW)] = v;
            p0 += HW; p1 += HW; p2 += HW; p3 += HW;
        }
    }
}

extern "C" void kernel_launch(void* const* d_in, const int* in_sizes, int n_in,
                              void* d_out, int out_size) {
    const float* x0    = (const float*)d_in[0];
    const float* x1    = (const float*)d_in[1];
    const float* x2    = (const float*)d_in[2];
    const float* x3    = (const float*)d_in[3];
    const float* boxes = (const float*)d_in[4];
    float* out = (float*)d_out;

    int R = in_sizes[4] / 4;    // B*N = 1024
    prep_kernel<<<(R + 255) / 256, 256>>>(boxes, R);
    pooler_kernel<<<R * PH, 256>>>(x0, x1, x2, x3, out, R);
}